// round 16
// baseline (speedup 1.0000x reference)
#include <cuda_runtime.h>
#include <cuda_fp16.h>
#include <math.h>
#include <stdint.h>

#define BB   4
#define LL   1024
#define BL   4096
#define DD   768
#define HH   12
#define DKH  64
#define FF   3072
#define MDIST 100
#define TBL  201
#define QN   2304   // combined QKV width

typedef __half fp16;

// ---------------- scratch ----------------
__device__ float g_pre[BL * DD];
__device__ float g_t1[BL * DD];
__device__ float g_bqkv[QN];

__device__ __align__(16) uint16_t g_idx[(size_t)BB * LL * LL];  // relpos idx / 0xFFFF mask

__device__ __align__(16) fp16 g_tokh[BL * DD];
__device__ __align__(16) fp16 g_qkvh[(size_t)BL * QN];
__device__ __align__(16) fp16 g_ctxh[BL * DD];
__device__ __align__(16) fp16 g_t1h[BL * DD];
__device__ __align__(16) fp16 g_ffh[(size_t)BL * FF];

__device__ __align__(16) fp16 g_wqkvh[(size_t)QN * DD];
__device__ __align__(16) fp16 g_woh[DD * DD];
__device__ __align__(16) fp16 g_w1h[(size_t)DD * FF];
__device__ __align__(16) fp16 g_w2h[(size_t)DD * FF];

// =================== helpers ===================
__device__ __forceinline__ uint32_t smem_u32(const void* p) {
    uint32_t a;
    asm("{ .reg .u64 t; cvta.to.shared.u64 t, %1; cvt.u32.u64 %0, t; }" : "=r"(a) : "l"(p));
    return a;
}
__device__ __forceinline__ void ldsm4(uint32_t* r, uint32_t addr) {
    asm volatile("ldmatrix.sync.aligned.m8n8.x4.shared.b16 {%0,%1,%2,%3}, [%4];"
        : "=r"(r[0]), "=r"(r[1]), "=r"(r[2]), "=r"(r[3]) : "r"(addr));
}
__device__ __forceinline__ void ldsm4t(uint32_t* r, uint32_t addr) {
    asm volatile("ldmatrix.sync.aligned.m8n8.x4.trans.shared.b16 {%0,%1,%2,%3}, [%4];"
        : "=r"(r[0]), "=r"(r[1]), "=r"(r[2]), "=r"(r[3]) : "r"(addr));
}
__device__ __forceinline__ void mma16816(float* d, const uint32_t* a, const uint32_t* b) {
    asm volatile("mma.sync.aligned.m16n8k16.row.col.f32.f16.f16.f32 "
        "{%0,%1,%2,%3}, {%4,%5,%6,%7}, {%8,%9}, {%0,%1,%2,%3};"
        : "+f"(d[0]), "+f"(d[1]), "+f"(d[2]), "+f"(d[3])
        : "r"(a[0]), "r"(a[1]), "r"(a[2]), "r"(a[3]), "r"(b[0]), "r"(b[1]));
}
__device__ __forceinline__ uint32_t pack2h(float a, float b) {
    __half2 h = __floats2half2_rn(a, b);
    return *(uint32_t*)&h;
}

// =================== conversions ===================
__global__ void __launch_bounds__(256)
cvt_split_bias(const float* __restrict__ X, fp16* __restrict__ H,
               int n4, const float* __restrict__ bq, const float* __restrict__ bk,
               const float* __restrict__ bv, float* __restrict__ bqkv)
{
    int i = blockIdx.x * 256 + threadIdx.x;
    if (i < n4) {
        float4 v = ((const float4*)X)[i];
        uint2 hh = {pack2h(v.x, v.y), pack2h(v.z, v.w)};
        ((uint2*)H)[i] = hh;
        return;
    }
    int j = i - n4;
    if (j < DD)           bqkv[j] = bq[j];
    else if (j < 2 * DD)  bqkv[j] = bk[j - DD];
    else if (j < 3 * DD)  bqkv[j] = bv[j - 2 * DD];
}

__global__ void __launch_bounds__(256)
idx_kernel(const float* __restrict__ pos, const float* __restrict__ amask,
           const unsigned char* __restrict__ pad, uint16_t* __restrict__ idx)
{
    size_t t = (size_t)blockIdx.x * 256 + threadIdx.x;
    size_t e0 = t * 4;
    int b = (int)(e0 >> 20);
    int r = (int)(e0 & (LL * (size_t)LL - 1));
    int q = r >> 10, k0 = r & 1023;

    float pxq = pos[2 * (size_t)(b * LL + q)];
    float pyq = pos[2 * (size_t)(b * LL + q) + 1];
    float4 am = *(const float4*)(amask + e0);
    float amv[4] = {am.x, am.y, am.z, am.w};

    uint16_t o[4];
    #pragma unroll
    for (int u = 0; u < 4; ++u) {
        int k = k0 + u;
        float pxk = pos[2 * (size_t)(b * LL + k)];
        float pyk = pos[2 * (size_t)(b * LL + k) + 1];
        float ddx = fminf(fmaxf(rintf(pxq - pxk), -(float)MDIST), (float)MDIST);
        float ddy = fminf(fmaxf(rintf(pyq - pyk), -(float)MDIST), (float)MDIST);
        int dx = (int)ddx + MDIST, dy = (int)ddy + MDIST;
        bool masked = (amv[u] == 0.0f) || (pad[b * LL + k] != 0);
        o[u] = masked ? 0xFFFFu : (uint16_t)(dy * TBL + dx);
    }
    *(uint2*)(idx + e0) = *(uint2*)o;
}

__global__ void __launch_bounds__(256)
cvt_wT4(const float* __restrict__ Wq, const float* __restrict__ Wk,
        const float* __restrict__ Wv, const float* __restrict__ Wo,
        fp16* __restrict__ qkvTH, fp16* __restrict__ oTH)
{
    __shared__ float t[32][33];
    const int z = blockIdx.z;
    const float* W = (z == 0) ? Wq : (z == 1) ? Wk : (z == 2) ? Wv : Wo;
    fp16* TH = (z < 3) ? (qkvTH + (size_t)z * DD * DD) : oTH;

    const int n0 = blockIdx.x * 32, k0 = blockIdx.y * 32;
    const int tx = threadIdx.x & 31, ty = threadIdx.x >> 5;
    #pragma unroll
    for (int i = 0; i < 4; ++i)
        t[ty + 8 * i][tx] = W[(size_t)(k0 + ty + 8 * i) * DD + n0 + tx];
    __syncthreads();
    #pragma unroll
    for (int i = 0; i < 4; ++i) {
        float x = t[tx][ty + 8 * i];
        TH[(size_t)(n0 + ty + 8 * i) * DD + k0 + tx] = __float2half_rn(x);
    }
}

__global__ void __launch_bounds__(256)
cvt_wT(const float* __restrict__ W, fp16* __restrict__ TH, int K, int N)
{
    __shared__ float t[32][33];
    const int n0 = blockIdx.x * 32, k0 = blockIdx.y * 32;
    const int tx = threadIdx.x & 31, ty = threadIdx.x >> 5;
    #pragma unroll
    for (int i = 0; i < 4; ++i)
        t[ty + 8 * i][tx] = W[(size_t)(k0 + ty + 8 * i) * N + n0 + tx];
    __syncthreads();
    #pragma unroll
    for (int i = 0; i < 4; ++i) {
        float x = t[tx][ty + 8 * i];
        TH[(size_t)(n0 + ty + 8 * i) * K + k0 + tx] = __float2half_rn(x);
    }
}

// =================== mma.sync fp16 GEMM (single-term weights) =================
#define AST 40

template<int EPI>
__global__ void __launch_bounds__(256)
gemm_mma(const fp16* __restrict__ A, const fp16* __restrict__ Bh,
         const float* __restrict__ bias, const float* __restrict__ res,
         float* __restrict__ C, fp16* __restrict__ Ch,
         int K, int N)
{
    __shared__ fp16 sA[128 * AST];
    __shared__ fp16 sB[128 * AST];

    const int tid = threadIdx.x, wid = tid >> 5, lane = tid & 31;
    const int m0 = blockIdx.y * 128, n0 = blockIdx.x * 128;
    const int wm = (wid >> 2) * 64;
    const int wn = (wid & 3) * 32;

    float acc[4][4][4] = {};

    uint4 pa[2], pb[2];

    const fp16* Ap = A  + (size_t)m0 * K;
    const fp16* Bp = Bh + (size_t)n0 * K;

    auto fetch = [&](int k0) {
        #pragma unroll
        for (int it = 0; it < 2; ++it) {
            int idx = tid + it * 256;
            int row = idx >> 2, g = idx & 3;
            size_t go = (size_t)row * K + k0 + g * 8;
            pa[it] = *(const uint4*)(Ap + go);
            pb[it] = *(const uint4*)(Bp + go);
        }
    };
    auto stage = [&]() {
        #pragma unroll
        for (int it = 0; it < 2; ++it) {
            int idx = tid + it * 256;
            int row = idx >> 2, g = idx & 3;
            *(uint4*)&sA[row * AST + g * 8] = pa[it];
            *(uint4*)&sB[row * AST + g * 8] = pb[it];
        }
    };

    const int a_row = wm + (lane & 15);
    const int a_kof = (lane >> 4) << 3;
    const int b_row = wn + ((lane >> 4) << 3) + (lane & 7);
    const int b_kof = ((lane >> 3) & 1) << 3;

    const uint32_t sA_b = smem_u32(sA), sB_b = smem_u32(sB);

    fetch(0);
    stage();
    __syncthreads();

    const int ns = K >> 5;
    for (int s = 0; s < ns; ++s) {
        if (s + 1 < ns) fetch((s + 1) << 5);

        #pragma unroll
        for (int kstep = 0; kstep < 2; ++kstep) {
            const int kk = kstep * 16;
            uint32_t af[4][4];
            #pragma unroll
            for (int mi = 0; mi < 4; ++mi) {
                uint32_t off = (uint32_t)((a_row + mi * 16) * AST + kk + a_kof) * 2;
                ldsm4(af[mi], sA_b + off);
            }
            uint32_t bf[2][4];
            #pragma unroll
            for (int g = 0; g < 2; ++g) {
                uint32_t off = (uint32_t)((b_row + g * 16) * AST + kk + b_kof) * 2;
                ldsm4(bf[g], sB_b + off);
            }
            #pragma unroll
            for (int mi = 0; mi < 4; ++mi)
                #pragma unroll
                for (int ni = 0; ni < 4; ++ni)
                    mma16816(acc[mi][ni], af[mi], &bf[ni >> 1][(ni & 1) * 2]);
        }

        __syncthreads();
        if (s + 1 < ns) {
            stage();
            __syncthreads();
        }
    }

    const int er = lane >> 2, ec = (lane & 3) * 2;
    #pragma unroll
    for (int mi = 0; mi < 4; ++mi) {
        #pragma unroll
        for (int hrow = 0; hrow < 2; ++hrow) {
            int row = m0 + wm + mi * 16 + er + hrow * 8;
            #pragma unroll
            for (int ni = 0; ni < 4; ++ni) {
                int col = n0 + wn + ni * 8 + ec;
                float v0 = acc[mi][ni][hrow * 2 + 0] + bias[col];
                float v1 = acc[mi][ni][hrow * 2 + 1] + bias[col + 1];
                if (EPI == 4) { v0 = fmaxf(v0, 0.0f); v1 = fmaxf(v1, 0.0f); }
                if (EPI == 2) {
                    v0 += res[(size_t)row * N + col];
                    v1 += res[(size_t)row * N + col + 1];
                    float2 o = {v0, v1};
                    *(float2*)(C + (size_t)row * N + col) = o;
                } else {
                    *(uint32_t*)(Ch + (size_t)row * N + col) = pack2h(v0, v1);
                }
            }
        }
    }
}

// =================== fused flash attention (q-tile 128, 256 thr) ==============
// K/V register-prefetch double buffering; precomputed relpos idx
#define FST 72

__global__ void __launch_bounds__(256)
flash_kernel(const fp16* __restrict__ qkvh, const float* __restrict__ pmask,
             const uint16_t* __restrict__ idx,
             const float* __restrict__ table, fp16* __restrict__ ctxh)
{
    __shared__ fp16 sK[64 * FST];
    __shared__ fp16 sV[64 * FST];
    __shared__ float pmq[128], pmk[64];

    const int q0 = blockIdx.x * 128;
    const int bh = blockIdx.y;
    const int b = bh / HH, h = bh % HH;
    const int tid = threadIdx.x, wid = tid >> 5, lane = tid & 31;
    const float* tbl = table + (size_t)h * TBL * TBL;

    const fp16* Qp = qkvh + (size_t)(b * LL) * QN + h * DKH;
    const fp16* Kp = Qp + DD;
    const fp16* Vp = Qp + 2 * DD;

    if (tid < 128) pmq[tid] = pmask[b * LL + q0 + tid];

    const uint32_t sK_b = smem_u32(sK), sV_b = smem_u32(sV);

    // ---- load Q fragments: two passes of 64 rows through sK ----
    uint32_t qf[4][4];
    #pragma unroll
    for (int pass = 0; pass < 2; ++pass) {
        #pragma unroll
        for (int it = 0; it < 2; ++it) {
            int i2 = tid + it * 256;
            int row = i2 >> 3, g = i2 & 7;
            size_t go = (size_t)(q0 + pass * 64 + row) * QN + g * 8;
            *(uint4*)&sK[row * FST + g * 8] = *(const uint4*)(Qp + go);
        }
        __syncthreads();
        if ((wid >> 2) == pass) {
            int a_row = (wid & 3) * 16 + (lane & 15);
            int a_kof = (lane >> 4) << 3;
            #pragma unroll
            for (int j = 0; j < 4; ++j) {
                uint32_t off = (uint32_t)(a_row * FST + j * 16 + a_kof) * 2;
                ldsm4(qf[j], sK_b + off);
            }
        }
        __syncthreads();
    }

    const int er = lane >> 2, ec = (lane & 3) * 2;
    const int qrl = (wid >> 2) * 64 + (wid & 3) * 16 + er;   // local q row
    const int qr0 = q0 + qrl;
    const uint16_t* idx0 = idx + ((size_t)b << 20) + (size_t)qr0 * LL;
    float mrow[2] = {-1e30f, -1e30f}, lrow[2] = {0.f, 0.f};
    float accO[8][4] = {};

    // K/V register prefetch
    uint4 pk, pv;
    float ppm;
    auto fetch_kv = [&](int k0) {
        int row = tid >> 1, g = (tid & 1) * 4;       // 256 thr: 128 half-rows... recompute:
        (void)row; (void)g;
        int i2 = tid;                                 // 512 uint4 total / 256 thr = 2, but split K/V
        int r2 = i2 >> 2, g2 = i2 & 3;               // 64 rows x 4 groups of 16B? 64*8*16B=8KB/arr
        (void)r2; (void)g2;
        int rr = tid >> 2, gg = (tid & 3) * 2;        // 64 rows, 4 x uint4-pairs? -> use 8 uint4/row
        (void)rr; (void)gg;
        int row8 = tid >> 2;                          // 0..63
        int g8 = (tid & 3) * 2;                       // 0,2,4,6 (each thread 2 uint4 K + 2 V? too many)
        (void)row8; (void)g8;
        // layout: 64 rows x 8 uint4 per array = 512 uint4 per array; 256 threads:
        // each thread does 2 uint4 of K and 2 of V -> keep regs small: do 1 K + 1 V per
        // iteration slot and use two slots via index math below.
        int i0 = tid;                 // first slot
        int r0 = i0 >> 2, g0 = (i0 & 3) * 2;   // covers rows 0..63, groups {0,2,4,6} (uint4 pairs)
        size_t go = (size_t)(k0 + r0) * QN + g0 * 8;
        pk = *(const uint4*)(Kp + go);
        pv = *(const uint4*)(Vp + go);
        // second 16B of the pair handled by +8 offset threads? No: groups g0*8 covers 16 halves
        // -> 4 slots of 16B*2 = 64 halves/row? row is 64 halves; g0 in {0,2,4,6}, each slot
        //    loads 8 halves at offset g0*8: covers 0,16,32,48 -> missing 8,24,40,56.
        ppm = (tid < 64) ? pmask[b * LL + k0 + tid] : 0.f;
    };
    // NOTE: the above covers only half the tile; fetch second halves separately:
    uint4 pk2, pv2;
    auto fetch_kv2 = [&](int k0) {
        int r0 = tid >> 2, g0 = (tid & 3) * 2 + 1;   // offsets 8,24,40,56
        size_t go = (size_t)(k0 + r0) * QN + g0 * 8;
        pk2 = *(const uint4*)(Kp + go);
        pv2 = *(const uint4*)(Vp + go);
    };
    auto stage_kv = [&](int k0) {
        int r0 = tid >> 2, g0 = (tid & 3) * 2;
        *(uint4*)&sK[r0 * FST + g0 * 8] = pk;
        *(uint4*)&sV[r0 * FST + g0 * 8] = pv;
        int g1 = g0 + 1;
        *(uint4*)&sK[r0 * FST + g1 * 8] = pk2;
        *(uint4*)&sV[r0 * FST + g1 * 8] = pv2;
        if (tid < 64) pmk[tid] = ppm;
        (void)k0;
    };

    fetch_kv(0);
    fetch_kv2(0);
    stage_kv(0);
    __syncthreads();

    for (int kt = 0; kt < 16; ++kt) {
        const int k0 = kt * 64;
        if (kt + 1 < 16) {
            fetch_kv((kt + 1) * 64);
            fetch_kv2((kt + 1) * 64);
        }

        // ---- S = Q K^T ----
        float accS[8][4] = {};
        #pragma unroll
        for (int j = 0; j < 4; ++j) {
            #pragma unroll
            for (int g = 0; g < 4; ++g) {
                uint32_t kf[4];
                int b_row = g * 16 + ((lane >> 4) << 3) + (lane & 7);
                uint32_t off = (uint32_t)(b_row * FST + j * 16 + (((lane >> 3) & 1) << 3)) * 2;
                ldsm4(kf, sK_b + off);
                mma16816(accS[2 * g],     qf[j], kf);
                mma16816(accS[2 * g + 1], qf[j], kf + 2);
            }
        }

        // ---- bias (precomputed idx) + online softmax ----
        float pmr[2] = {pmq[qrl], pmq[qrl + 8]};
        float newm[2] = {mrow[0], mrow[1]};
        #pragma unroll
        for (int ni = 0; ni < 8; ++ni) {
            #pragma unroll
            for (int r = 0; r < 2; ++r) {
                int kj0 = ni * 8 + ec;
                uint32_t ii = *(const uint32_t*)(idx0 + (size_t)(8 * r) * LL + k0 + kj0);
                uint32_t i0 = ii & 0xFFFFu, i1 = ii >> 16;
                float s0 = accS[ni][2 * r + 0] * 0.125f;
                float s1 = accS[ni][2 * r + 1] * 0.125f;
                s0 = (i0 == 0xFFFFu) ? -1e9f : s0 + tbl[i0] * (pmr[r] * pmk[kj0]);
                s1 = (i1 == 0xFFFFu) ? -1e9f : s1 + tbl[i1] * (pmr[r] * pmk[kj0 + 1]);
                accS[ni][2 * r + 0] = s0;
                accS[ni][2 * r + 1] = s1;
                newm[r] = fmaxf(newm[r], fmaxf(s0, s1));
            }
        }
        #pragma unroll
        for (int r = 0; r < 2; ++r) {
            newm[r] = fmaxf(newm[r], __shfl_xor_sync(0xffffffffu, newm[r], 1));
            newm[r] = fmaxf(newm[r], __shfl_xor_sync(0xffffffffu, newm[r], 2));
        }
        float alpha[2], psum[2] = {0.f, 0.f};
        #pragma unroll
        for (int r = 0; r < 2; ++r) {
            alpha[r] = __expf(mrow[r] - newm[r]);
            mrow[r] = newm[r];
        }
        #pragma unroll
        for (int ni = 0; ni < 8; ++ni)
            #pragma unroll
            for (int u = 0; u < 4; ++u) {
                float p = __expf(accS[ni][u] - newm[u >> 1]);
                accS[ni][u] = p;
                psum[u >> 1] += p;
            }
        #pragma unroll
        for (int r = 0; r < 2; ++r) {
            psum[r] += __shfl_xor_sync(0xffffffffu, psum[r], 1);
            psum[r] += __shfl_xor_sync(0xffffffffu, psum[r], 2);
            lrow[r] = lrow[r] * alpha[r] + psum[r];
        }
        #pragma unroll
        for (int ni = 0; ni < 8; ++ni)
            #pragma unroll
            for (int u = 0; u < 4; ++u)
                accO[ni][u] *= alpha[u >> 1];

        // ---- O += P V ----
        #pragma unroll
        for (int j = 0; j < 4; ++j) {
            uint32_t af[4];
            af[0] = pack2h(accS[2 * j][0],     accS[2 * j][1]);
            af[1] = pack2h(accS[2 * j][2],     accS[2 * j][3]);
            af[2] = pack2h(accS[2 * j + 1][0], accS[2 * j + 1][1]);
            af[3] = pack2h(accS[2 * j + 1][2], accS[2 * j + 1][3]);
            #pragma unroll
            for (int g = 0; g < 4; ++g) {
                uint32_t vf[4];
                uint32_t off = (uint32_t)((j * 16 + (lane & 15)) * FST + g * 16 + ((lane >> 4) << 3)) * 2;
                ldsm4t(vf, sV_b + off);
                mma16816(accO[2 * g],     af, vf);
                mma16816(accO[2 * g + 1], af, vf + 2);
            }
        }
        __syncthreads();
        if (kt + 1 < 16) {
            stage_kv((kt + 1) * 64);
            __syncthreads();
        }
    }

    #pragma unroll
    for (int r = 0; r < 2; ++r) {
        float inv = 1.f / lrow[r];
        #pragma unroll
        for (int ni = 0; ni < 8; ++ni) {
            size_t o = (size_t)(b * LL + qr0 + 8 * r) * DD + h * DKH + ni * 8 + ec;
            *(uint32_t*)(ctxh + o) = pack2h(accO[ni][2 * r] * inv, accO[ni][2 * r + 1] * inv);
        }
    }
}

// ------------- LayerNorm ------------------------------------------------------
template<bool SPLIT>
__global__ void __launch_bounds__(256)
ln_kernel(const float* __restrict__ X, const float* __restrict__ g,
          const float* __restrict__ bt, float* __restrict__ O,
          fp16* __restrict__ Oh)
{
    const int row = blockIdx.x;
    const float* x = X + (size_t)row * DD;
    const int tid = threadIdx.x;

    float v[3];
    #pragma unroll
    for (int i = 0; i < 3; ++i) v[i] = x[tid + i * 256];

    __shared__ float red[256];
    float s = v[0] + v[1] + v[2];
    red[tid] = s; __syncthreads();
    for (int st = 128; st > 0; st >>= 1) {
        if (tid < st) red[tid] += red[tid + st];
        __syncthreads();
    }
    float mean = red[0] * (1.0f / DD);
    __syncthreads();

    float d0 = v[0] - mean, d1 = v[1] - mean, d2 = v[2] - mean;
    red[tid] = d0 * d0 + d1 * d1 + d2 * d2; __syncthreads();
    for (int st = 128; st > 0; st >>= 1) {
        if (tid < st) red[tid] += red[tid + st];
        __syncthreads();
    }
    float var = red[0] * (1.0f / DD);
    float inv = rsqrtf(var + 1e-5f);

    #pragma unroll
    for (int i = 0; i < 3; ++i) {
        int c = tid + i * 256;
        float o = (v[i] - mean) * inv * g[c] + bt[c];
        O[(size_t)row * DD + c] = o;
        if (SPLIT) Oh[(size_t)row * DD + c] = __float2half_rn(o);
    }
}

// ------------------------------- launch ---------------------------------------
extern "C" void kernel_launch(void* const* d_in, const int* in_sizes, int n_in,
                              void* d_out, int out_size)
{
    const float* tokens = (const float*)d_in[0];
    const float* pos    = (const float*)d_in[1];
    const float* pmask  = (const float*)d_in[2];
    const float* amask  = (const float*)d_in[3];
    const unsigned char* pad = (const unsigned char*)d_in[4];
    const float* Wq = (const float*)d_in[5];
    const float* bq = (const float*)d_in[6];
    const float* Wk = (const float*)d_in[7];
    const float* bk = (const float*)d_in[8];
    const float* Wv = (const float*)d_in[9];
    const float* bv = (const float*)d_in[10];
    const float* Wo = (const float*)d_in[11];
    const float* bo = (const float*)d_in[12];
    const float* table = (const float*)d_in[13];
    const float* W1 = (const float*)d_in[14];
    const float* b1 = (const float*)d_in[15];
    const float* W2 = (const float*)d_in[16];
    const float* b2 = (const float*)d_in[17];
    const float* ln1g = (const float*)d_in[18];
    const float* ln1b = (const float*)d_in[19];
    const float* ln2g = (const float*)d_in[20];
    const float* ln2b = (const float*)d_in[21];
    float* out = (float*)d_out;

    float *Pb, *Tb, *bqkv;
    cudaGetSymbolAddress((void**)&Pb, g_pre);
    cudaGetSymbolAddress((void**)&Tb, g_t1);
    cudaGetSymbolAddress((void**)&bqkv, g_bqkv);

    uint16_t* idxb;
    cudaGetSymbolAddress((void**)&idxb, g_idx);

    fp16 *tokh, *qkvh, *ctxh, *t1h, *ffh;
    cudaGetSymbolAddress((void**)&tokh, g_tokh);
    cudaGetSymbolAddress((void**)&qkvh, g_qkvh);
    cudaGetSymbolAddress((void**)&ctxh, g_ctxh);
    cudaGetSymbolAddress((void**)&t1h, g_t1h);
    cudaGetSymbolAddress((void**)&ffh, g_ffh);

    fp16 *wqkvh, *woh, *w1h, *w2h;
    cudaGetSymbolAddress((void**)&wqkvh, g_wqkvh);
    cudaGetSymbolAddress((void**)&woh, g_woh);
    cudaGetSymbolAddress((void**)&w1h, g_w1h);
    cudaGetSymbolAddress((void**)&w2h, g_w2h);

    // prep
    cvt_wT4<<<dim3(DD / 32, DD / 32, 4), 256>>>(Wq, Wk, Wv, Wo, wqkvh, woh);
    cvt_wT<<<dim3(FF / 32, DD / 32), 256>>>(W1, w1h, DD, FF);
    cvt_wT<<<dim3(DD / 32, FF / 32), 256>>>(W2, w2h, FF, DD);
    {
        int n4 = BL * DD / 4;
        int nblk = (n4 + QN + 255) / 256;
        cvt_split_bias<<<nblk, 256>>>(tokens, tokh, n4, bq, bk, bv, bqkv);
    }
    idx_kernel<<<(int)(((size_t)BB * LL * LL / 4 + 255) / 256), 256>>>(pos, amask, pad, idxb);

    // fused QKV GEMM -> fp16
    gemm_mma<3><<<dim3(QN / 128, BL / 128), 256>>>(tokh, wqkvh, bqkv,
                                                   nullptr, nullptr, qkvh, DD, QN);

    // fused attention -> ctx fp16 (q-tile 128, double-buffered staging)
    dim3 gfa(LL / 128, BB * HH);
    flash_kernel<<<gfa, 256>>>(qkvh, pmask, idxb, table, ctxh);

    // out proj + residual -> fp32, LN1 (emits fp32 + fp16)
    gemm_mma<2><<<dim3(DD / 128, BL / 128), 256>>>(ctxh, woh, bo,
                                                   tokens, Pb, nullptr, DD, DD);
    ln_kernel<true><<<BL, 256>>>(Pb, ln1g, ln1b, Tb, t1h);

    // FFN
    gemm_mma<4><<<dim3(FF / 128, BL / 128), 256>>>(t1h, w1h, b1,
                                                   nullptr, nullptr, ffh, DD, FF);
    gemm_mma<2><<<dim3(DD / 128, BL / 128), 256>>>(ffh, w2h, b2,
                                                   Tb, Pb, nullptr, FF, DD);
    ln_kernel<false><<<BL, 256>>>(Pb, ln2g, ln2b, out, nullptr);
}

// round 17
// speedup vs baseline: 1.0221x; 1.0221x over previous
#include <cuda_runtime.h>
#include <cuda_fp16.h>
#include <math.h>
#include <stdint.h>

#define BB   4
#define LL   1024
#define BL   4096
#define DD   768
#define HH   12
#define DKH  64
#define FF   3072
#define MDIST 100
#define TBL  201
#define QN   2304   // combined QKV width

typedef __half fp16;

// ---------------- scratch ----------------
__device__ float g_pre[BL * DD];
__device__ float g_t1[BL * DD];
__device__ float g_bqkv[QN];

__device__ __align__(16) uint16_t g_idx[(size_t)BB * LL * LL];  // relpos idx / 0xFFFF mask

__device__ __align__(16) fp16 g_tokh[BL * DD];
__device__ __align__(16) fp16 g_qkvh[(size_t)BL * QN];
__device__ __align__(16) fp16 g_ctxh[BL * DD];
__device__ __align__(16) fp16 g_t1h[BL * DD];
__device__ __align__(16) fp16 g_ffh[(size_t)BL * FF];

__device__ __align__(16) fp16 g_wqkvh[(size_t)QN * DD];
__device__ __align__(16) fp16 g_woh[DD * DD];
__device__ __align__(16) fp16 g_w1h[(size_t)DD * FF];
__device__ __align__(16) fp16 g_w2h[(size_t)DD * FF];

// =================== helpers ===================
__device__ __forceinline__ uint32_t smem_u32(const void* p) {
    uint32_t a;
    asm("{ .reg .u64 t; cvta.to.shared.u64 t, %1; cvt.u32.u64 %0, t; }" : "=r"(a) : "l"(p));
    return a;
}
__device__ __forceinline__ void ldsm4(uint32_t* r, uint32_t addr) {
    asm volatile("ldmatrix.sync.aligned.m8n8.x4.shared.b16 {%0,%1,%2,%3}, [%4];"
        : "=r"(r[0]), "=r"(r[1]), "=r"(r[2]), "=r"(r[3]) : "r"(addr));
}
__device__ __forceinline__ void ldsm4t(uint32_t* r, uint32_t addr) {
    asm volatile("ldmatrix.sync.aligned.m8n8.x4.trans.shared.b16 {%0,%1,%2,%3}, [%4];"
        : "=r"(r[0]), "=r"(r[1]), "=r"(r[2]), "=r"(r[3]) : "r"(addr));
}
__device__ __forceinline__ void mma16816(float* d, const uint32_t* a, const uint32_t* b) {
    asm volatile("mma.sync.aligned.m16n8k16.row.col.f32.f16.f16.f32 "
        "{%0,%1,%2,%3}, {%4,%5,%6,%7}, {%8,%9}, {%0,%1,%2,%3};"
        : "+f"(d[0]), "+f"(d[1]), "+f"(d[2]), "+f"(d[3])
        : "r"(a[0]), "r"(a[1]), "r"(a[2]), "r"(a[3]), "r"(b[0]), "r"(b[1]));
}
__device__ __forceinline__ uint32_t pack2h(float a, float b) {
    __half2 h = __floats2half2_rn(a, b);
    return *(uint32_t*)&h;
}

// =================== conversions ===================
__global__ void __launch_bounds__(256)
cvt_split_bias(const float* __restrict__ X, fp16* __restrict__ H,
               int n4, const float* __restrict__ bq, const float* __restrict__ bk,
               const float* __restrict__ bv, float* __restrict__ bqkv)
{
    int i = blockIdx.x * 256 + threadIdx.x;
    if (i < n4) {
        float4 v = ((const float4*)X)[i];
        uint2 hh = {pack2h(v.x, v.y), pack2h(v.z, v.w)};
        ((uint2*)H)[i] = hh;
        return;
    }
    int j = i - n4;
    if (j < DD)           bqkv[j] = bq[j];
    else if (j < 2 * DD)  bqkv[j] = bk[j - DD];
    else if (j < 3 * DD)  bqkv[j] = bv[j - 2 * DD];
}

__global__ void __launch_bounds__(256)
idx_kernel(const float* __restrict__ pos, const float* __restrict__ amask,
           const unsigned char* __restrict__ pad, uint16_t* __restrict__ idx)
{
    size_t t = (size_t)blockIdx.x * 256 + threadIdx.x;
    size_t e0 = t * 4;
    int b = (int)(e0 >> 20);
    int r = (int)(e0 & (LL * (size_t)LL - 1));
    int q = r >> 10, k0 = r & 1023;

    float pxq = pos[2 * (size_t)(b * LL + q)];
    float pyq = pos[2 * (size_t)(b * LL + q) + 1];
    float4 am = *(const float4*)(amask + e0);
    float amv[4] = {am.x, am.y, am.z, am.w};

    uint16_t o[4];
    #pragma unroll
    for (int u = 0; u < 4; ++u) {
        int k = k0 + u;
        float pxk = pos[2 * (size_t)(b * LL + k)];
        float pyk = pos[2 * (size_t)(b * LL + k) + 1];
        float ddx = fminf(fmaxf(rintf(pxq - pxk), -(float)MDIST), (float)MDIST);
        float ddy = fminf(fmaxf(rintf(pyq - pyk), -(float)MDIST), (float)MDIST);
        int dx = (int)ddx + MDIST, dy = (int)ddy + MDIST;
        bool masked = (amv[u] == 0.0f) || (pad[b * LL + k] != 0);
        o[u] = masked ? 0xFFFFu : (uint16_t)(dy * TBL + dx);
    }
    *(uint2*)(idx + e0) = *(uint2*)o;
}

__global__ void __launch_bounds__(256)
cvt_wT4(const float* __restrict__ Wq, const float* __restrict__ Wk,
        const float* __restrict__ Wv, const float* __restrict__ Wo,
        fp16* __restrict__ qkvTH, fp16* __restrict__ oTH)
{
    __shared__ float t[32][33];
    const int z = blockIdx.z;
    const float* W = (z == 0) ? Wq : (z == 1) ? Wk : (z == 2) ? Wv : Wo;
    fp16* TH = (z < 3) ? (qkvTH + (size_t)z * DD * DD) : oTH;

    const int n0 = blockIdx.x * 32, k0 = blockIdx.y * 32;
    const int tx = threadIdx.x & 31, ty = threadIdx.x >> 5;
    #pragma unroll
    for (int i = 0; i < 4; ++i)
        t[ty + 8 * i][tx] = W[(size_t)(k0 + ty + 8 * i) * DD + n0 + tx];
    __syncthreads();
    #pragma unroll
    for (int i = 0; i < 4; ++i) {
        float x = t[tx][ty + 8 * i];
        TH[(size_t)(n0 + ty + 8 * i) * DD + k0 + tx] = __float2half_rn(x);
    }
}

__global__ void __launch_bounds__(256)
cvt_wT(const float* __restrict__ W, fp16* __restrict__ TH, int K, int N)
{
    __shared__ float t[32][33];
    const int n0 = blockIdx.x * 32, k0 = blockIdx.y * 32;
    const int tx = threadIdx.x & 31, ty = threadIdx.x >> 5;
    #pragma unroll
    for (int i = 0; i < 4; ++i)
        t[ty + 8 * i][tx] = W[(size_t)(k0 + ty + 8 * i) * N + n0 + tx];
    __syncthreads();
    #pragma unroll
    for (int i = 0; i < 4; ++i) {
        float x = t[tx][ty + 8 * i];
        TH[(size_t)(n0 + ty + 8 * i) * K + k0 + tx] = __float2half_rn(x);
    }
}

// ========== mma.sync fp16 GEMM, double-buffered smem, 1 sync/iter ==========
#define AST 40

template<int EPI>
__global__ void __launch_bounds__(256)
gemm_mma(const fp16* __restrict__ A, const fp16* __restrict__ Bh,
         const float* __restrict__ bias, const float* __restrict__ res,
         float* __restrict__ C, fp16* __restrict__ Ch,
         int K, int N)
{
    __shared__ fp16 sA[2][128 * AST];
    __shared__ fp16 sB[2][128 * AST];

    const int tid = threadIdx.x, wid = tid >> 5, lane = tid & 31;
    const int m0 = blockIdx.y * 128, n0 = blockIdx.x * 128;
    const int wm = (wid >> 2) * 64;
    const int wn = (wid & 3) * 32;

    float acc[4][4][4] = {};

    uint4 pa[2], pb[2];

    const fp16* Ap = A  + (size_t)m0 * K;
    const fp16* Bp = Bh + (size_t)n0 * K;

    auto fetch = [&](int k0) {
        #pragma unroll
        for (int it = 0; it < 2; ++it) {
            int idx = tid + it * 256;
            int row = idx >> 2, g = idx & 3;
            size_t go = (size_t)row * K + k0 + g * 8;
            pa[it] = *(const uint4*)(Ap + go);
            pb[it] = *(const uint4*)(Bp + go);
        }
    };
    auto stage = [&](int buf) {
        #pragma unroll
        for (int it = 0; it < 2; ++it) {
            int idx = tid + it * 256;
            int row = idx >> 2, g = idx & 3;
            *(uint4*)&sA[buf][row * AST + g * 8] = pa[it];
            *(uint4*)&sB[buf][row * AST + g * 8] = pb[it];
        }
    };

    const int a_row = wm + (lane & 15);
    const int a_kof = (lane >> 4) << 3;
    const int b_row = wn + ((lane >> 4) << 3) + (lane & 7);
    const int b_kof = ((lane >> 3) & 1) << 3;

    fetch(0);
    stage(0);
    __syncthreads();

    const int ns = K >> 5;
    for (int s = 0; s < ns; ++s) {
        const int buf = s & 1;
        const uint32_t sA_b = smem_u32(sA[buf]);
        const uint32_t sB_b = smem_u32(sB[buf]);

        if (s + 1 < ns) fetch((s + 1) << 5);

        #pragma unroll
        for (int kstep = 0; kstep < 2; ++kstep) {
            const int kk = kstep * 16;
            uint32_t af[4][4];
            #pragma unroll
            for (int mi = 0; mi < 4; ++mi) {
                uint32_t off = (uint32_t)((a_row + mi * 16) * AST + kk + a_kof) * 2;
                ldsm4(af[mi], sA_b + off);
            }
            uint32_t bf[2][4];
            #pragma unroll
            for (int g = 0; g < 2; ++g) {
                uint32_t off = (uint32_t)((b_row + g * 16) * AST + kk + b_kof) * 2;
                ldsm4(bf[g], sB_b + off);
            }
            #pragma unroll
            for (int mi = 0; mi < 4; ++mi)
                #pragma unroll
                for (int ni = 0; ni < 4; ++ni)
                    mma16816(acc[mi][ni], af[mi], &bf[ni >> 1][(ni & 1) * 2]);
        }

        if (s + 1 < ns) stage(buf ^ 1);   // writes other buffer: no hazard with reads
        __syncthreads();
    }

    const int er = lane >> 2, ec = (lane & 3) * 2;
    #pragma unroll
    for (int mi = 0; mi < 4; ++mi) {
        #pragma unroll
        for (int hrow = 0; hrow < 2; ++hrow) {
            int row = m0 + wm + mi * 16 + er + hrow * 8;
            #pragma unroll
            for (int ni = 0; ni < 4; ++ni) {
                int col = n0 + wn + ni * 8 + ec;
                float v0 = acc[mi][ni][hrow * 2 + 0] + bias[col];
                float v1 = acc[mi][ni][hrow * 2 + 1] + bias[col + 1];
                if (EPI == 4) { v0 = fmaxf(v0, 0.0f); v1 = fmaxf(v1, 0.0f); }
                if (EPI == 2) {
                    v0 += res[(size_t)row * N + col];
                    v1 += res[(size_t)row * N + col + 1];
                    float2 o = {v0, v1};
                    *(float2*)(C + (size_t)row * N + col) = o;
                } else {
                    *(uint32_t*)(Ch + (size_t)row * N + col) = pack2h(v0, v1);
                }
            }
        }
    }
}

// =================== fused flash attention (R15 winner: q64, 128 thr) =========
#define FST 72

__global__ void __launch_bounds__(128)
flash_kernel(const fp16* __restrict__ qkvh, const float* __restrict__ pmask,
             const uint16_t* __restrict__ idx,
             const float* __restrict__ table, fp16* __restrict__ ctxh)
{
    __shared__ fp16 sK[64 * FST];
    __shared__ fp16 sV[64 * FST];
    __shared__ float pmq[64], pmk[64];

    const int q0 = blockIdx.x * 64;
    const int bh = blockIdx.y;
    const int b = bh / HH, h = bh % HH;
    const int tid = threadIdx.x, wid = tid >> 5, lane = tid & 31;
    const float* tbl = table + (size_t)h * TBL * TBL;

    const fp16* Qp = qkvh + (size_t)(b * LL) * QN + h * DKH;
    const fp16* Kp = Qp + DD;
    const fp16* Vp = Qp + 2 * DD;

    if (tid < 64) pmq[tid] = pmask[b * LL + q0 + tid];

    #pragma unroll
    for (int it = 0; it < 4; ++it) {
        int i2 = tid + it * 128;
        int row = i2 >> 3, g = i2 & 7;
        size_t go = (size_t)(q0 + row) * QN + g * 8;
        *(uint4*)&sK[row * FST + g * 8] = *(const uint4*)(Qp + go);
    }
    __syncthreads();

    const uint32_t sK_b = smem_u32(sK), sV_b = smem_u32(sV);

    uint32_t qf[4][4];
    {
        int a_row = wid * 16 + (lane & 15);
        int a_kof = (lane >> 4) << 3;
        #pragma unroll
        for (int j = 0; j < 4; ++j) {
            uint32_t off = (uint32_t)(a_row * FST + j * 16 + a_kof) * 2;
            ldsm4(qf[j], sK_b + off);
        }
    }
    __syncthreads();

    const int er = lane >> 2, ec = (lane & 3) * 2;
    const int qr0 = q0 + wid * 16 + er;
    const uint16_t* idx0 = idx + ((size_t)b << 20) + (size_t)qr0 * LL;
    float mrow[2] = {-1e30f, -1e30f}, lrow[2] = {0.f, 0.f};
    float accO[8][4] = {};

    for (int kt = 0; kt < 16; ++kt) {
        const int k0 = kt * 64;
        #pragma unroll
        for (int it = 0; it < 4; ++it) {
            int i2 = tid + it * 128;
            int row = i2 >> 3, g = i2 & 7;
            size_t go = (size_t)(k0 + row) * QN + g * 8;
            *(uint4*)&sK[row * FST + g * 8] = *(const uint4*)(Kp + go);
            *(uint4*)&sV[row * FST + g * 8] = *(const uint4*)(Vp + go);
        }
        if (tid < 64) pmk[tid] = pmask[b * LL + k0 + tid];
        __syncthreads();

        // ---- S = Q K^T ----
        float accS[8][4] = {};
        #pragma unroll
        for (int j = 0; j < 4; ++j) {
            #pragma unroll
            for (int g = 0; g < 4; ++g) {
                uint32_t kf[4];
                int b_row = g * 16 + ((lane >> 4) << 3) + (lane & 7);
                uint32_t off = (uint32_t)(b_row * FST + j * 16 + (((lane >> 3) & 1) << 3)) * 2;
                ldsm4(kf, sK_b + off);
                mma16816(accS[2 * g],     qf[j], kf);
                mma16816(accS[2 * g + 1], qf[j], kf + 2);
            }
        }

        // ---- bias (precomputed idx) + online softmax ----
        float pmr[2] = {pmq[wid * 16 + er], pmq[wid * 16 + er + 8]};
        float newm[2] = {mrow[0], mrow[1]};
        #pragma unroll
        for (int ni = 0; ni < 8; ++ni) {
            #pragma unroll
            for (int r = 0; r < 2; ++r) {
                int kj0 = ni * 8 + ec;
                uint32_t ii = *(const uint32_t*)(idx0 + (size_t)(8 * r) * LL + k0 + kj0);
                uint32_t i0 = ii & 0xFFFFu, i1 = ii >> 16;
                float s0 = accS[ni][2 * r + 0] * 0.125f;
                float s1 = accS[ni][2 * r + 1] * 0.125f;
                s0 = (i0 == 0xFFFFu) ? -1e9f : s0 + tbl[i0] * (pmr[r] * pmk[kj0]);
                s1 = (i1 == 0xFFFFu) ? -1e9f : s1 + tbl[i1] * (pmr[r] * pmk[kj0 + 1]);
                accS[ni][2 * r + 0] = s0;
                accS[ni][2 * r + 1] = s1;
                newm[r] = fmaxf(newm[r], fmaxf(s0, s1));
            }
        }
        #pragma unroll
        for (int r = 0; r < 2; ++r) {
            newm[r] = fmaxf(newm[r], __shfl_xor_sync(0xffffffffu, newm[r], 1));
            newm[r] = fmaxf(newm[r], __shfl_xor_sync(0xffffffffu, newm[r], 2));
        }
        float alpha[2], psum[2] = {0.f, 0.f};
        #pragma unroll
        for (int r = 0; r < 2; ++r) {
            alpha[r] = __expf(mrow[r] - newm[r]);
            mrow[r] = newm[r];
        }
        #pragma unroll
        for (int ni = 0; ni < 8; ++ni)
            #pragma unroll
            for (int u = 0; u < 4; ++u) {
                float p = __expf(accS[ni][u] - newm[u >> 1]);
                accS[ni][u] = p;
                psum[u >> 1] += p;
            }
        #pragma unroll
        for (int r = 0; r < 2; ++r) {
            psum[r] += __shfl_xor_sync(0xffffffffu, psum[r], 1);
            psum[r] += __shfl_xor_sync(0xffffffffu, psum[r], 2);
            lrow[r] = lrow[r] * alpha[r] + psum[r];
        }
        #pragma unroll
        for (int ni = 0; ni < 8; ++ni)
            #pragma unroll
            for (int u = 0; u < 4; ++u)
                accO[ni][u] *= alpha[u >> 1];

        // ---- O += P V ----
        #pragma unroll
        for (int j = 0; j < 4; ++j) {
            uint32_t af[4];
            af[0] = pack2h(accS[2 * j][0],     accS[2 * j][1]);
            af[1] = pack2h(accS[2 * j][2],     accS[2 * j][3]);
            af[2] = pack2h(accS[2 * j + 1][0], accS[2 * j + 1][1]);
            af[3] = pack2h(accS[2 * j + 1][2], accS[2 * j + 1][3]);
            #pragma unroll
            for (int g = 0; g < 4; ++g) {
                uint32_t vf[4];
                uint32_t off = (uint32_t)((j * 16 + (lane & 15)) * FST + g * 16 + ((lane >> 4) << 3)) * 2;
                ldsm4t(vf, sV_b + off);
                mma16816(accO[2 * g],     af, vf);
                mma16816(accO[2 * g + 1], af, vf + 2);
            }
        }
        __syncthreads();
    }

    #pragma unroll
    for (int r = 0; r < 2; ++r) {
        float inv = 1.f / lrow[r];
        #pragma unroll
        for (int ni = 0; ni < 8; ++ni) {
            size_t o = (size_t)(b * LL + qr0 + 8 * r) * DD + h * DKH + ni * 8 + ec;
            *(uint32_t*)(ctxh + o) = pack2h(accO[ni][2 * r] * inv, accO[ni][2 * r + 1] * inv);
        }
    }
}

// ------------- LayerNorm ------------------------------------------------------
template<bool SPLIT>
__global__ void __launch_bounds__(256)
ln_kernel(const float* __restrict__ X, const float* __restrict__ g,
          const float* __restrict__ bt, float* __restrict__ O,
          fp16* __restrict__ Oh)
{
    const int row = blockIdx.x;
    const float* x = X + (size_t)row * DD;
    const int tid = threadIdx.x;

    float v[3];
    #pragma unroll
    for (int i = 0; i < 3; ++i) v[i] = x[tid + i * 256];

    __shared__ float red[256];
    float s = v[0] + v[1] + v[2];
    red[tid] = s; __syncthreads();
    for (int st = 128; st > 0; st >>= 1) {
        if (tid < st) red[tid] += red[tid + st];
        __syncthreads();
    }
    float mean = red[0] * (1.0f / DD);
    __syncthreads();

    float d0 = v[0] - mean, d1 = v[1] - mean, d2 = v[2] - mean;
    red[tid] = d0 * d0 + d1 * d1 + d2 * d2; __syncthreads();
    for (int st = 128; st > 0; st >>= 1) {
        if (tid < st) red[tid] += red[tid + st];
        __syncthreads();
    }
    float var = red[0] * (1.0f / DD);
    float inv = rsqrtf(var + 1e-5f);

    #pragma unroll
    for (int i = 0; i < 3; ++i) {
        int c = tid + i * 256;
        float o = (v[i] - mean) * inv * g[c] + bt[c];
        O[(size_t)row * DD + c] = o;
        if (SPLIT) Oh[(size_t)row * DD + c] = __float2half_rn(o);
    }
}

// ------------------------------- launch ---------------------------------------
extern "C" void kernel_launch(void* const* d_in, const int* in_sizes, int n_in,
                              void* d_out, int out_size)
{
    const float* tokens = (const float*)d_in[0];
    const float* pos    = (const float*)d_in[1];
    const float* pmask  = (const float*)d_in[2];
    const float* amask  = (const float*)d_in[3];
    const unsigned char* pad = (const unsigned char*)d_in[4];
    const float* Wq = (const float*)d_in[5];
    const float* bq = (const float*)d_in[6];
    const float* Wk = (const float*)d_in[7];
    const float* bk = (const float*)d_in[8];
    const float* Wv = (const float*)d_in[9];
    const float* bv = (const float*)d_in[10];
    const float* Wo = (const float*)d_in[11];
    const float* bo = (const float*)d_in[12];
    const float* table = (const float*)d_in[13];
    const float* W1 = (const float*)d_in[14];
    const float* b1 = (const float*)d_in[15];
    const float* W2 = (const float*)d_in[16];
    const float* b2 = (const float*)d_in[17];
    const float* ln1g = (const float*)d_in[18];
    const float* ln1b = (const float*)d_in[19];
    const float* ln2g = (const float*)d_in[20];
    const float* ln2b = (const float*)d_in[21];
    float* out = (float*)d_out;

    float *Pb, *Tb, *bqkv;
    cudaGetSymbolAddress((void**)&Pb, g_pre);
    cudaGetSymbolAddress((void**)&Tb, g_t1);
    cudaGetSymbolAddress((void**)&bqkv, g_bqkv);

    uint16_t* idxb;
    cudaGetSymbolAddress((void**)&idxb, g_idx);

    fp16 *tokh, *qkvh, *ctxh, *t1h, *ffh;
    cudaGetSymbolAddress((void**)&tokh, g_tokh);
    cudaGetSymbolAddress((void**)&qkvh, g_qkvh);
    cudaGetSymbolAddress((void**)&ctxh, g_ctxh);
    cudaGetSymbolAddress((void**)&t1h, g_t1h);
    cudaGetSymbolAddress((void**)&ffh, g_ffh);

    fp16 *wqkvh, *woh, *w1h, *w2h;
    cudaGetSymbolAddress((void**)&wqkvh, g_wqkvh);
    cudaGetSymbolAddress((void**)&woh, g_woh);
    cudaGetSymbolAddress((void**)&w1h, g_w1h);
    cudaGetSymbolAddress((void**)&w2h, g_w2h);

    // prep
    cvt_wT4<<<dim3(DD / 32, DD / 32, 4), 256>>>(Wq, Wk, Wv, Wo, wqkvh, woh);
    cvt_wT<<<dim3(FF / 32, DD / 32), 256>>>(W1, w1h, DD, FF);
    cvt_wT<<<dim3(DD / 32, FF / 32), 256>>>(W2, w2h, FF, DD);
    {
        int n4 = BL * DD / 4;
        int nblk = (n4 + QN + 255) / 256;
        cvt_split_bias<<<nblk, 256>>>(tokens, tokh, n4, bq, bk, bv, bqkv);
    }
    idx_kernel<<<(int)(((size_t)BB * LL * LL / 4 + 255) / 256), 256>>>(pos, amask, pad, idxb);

    // fused QKV GEMM -> fp16
    gemm_mma<3><<<dim3(QN / 128, BL / 128), 256>>>(tokh, wqkvh, bqkv,
                                                   nullptr, nullptr, qkvh, DD, QN);

    // fused attention -> ctx fp16
    dim3 gfa(LL / 64, BB * HH);
    flash_kernel<<<gfa, 128>>>(qkvh, pmask, idxb, table, ctxh);

    // out proj + residual -> fp32, LN1 (emits fp32 + fp16)
    gemm_mma<2><<<dim3(DD / 128, BL / 128), 256>>>(ctxh, woh, bo,
                                                   tokens, Pb, nullptr, DD, DD);
    ln_kernel<true><<<BL, 256>>>(Pb, ln1g, ln1b, Tb, t1h);

    // FFN
    gemm_mma<4><<<dim3(FF / 128, BL / 128), 256>>>(t1h, w1h, b1,
                                                   nullptr, nullptr, ffh, DD, FF);
    gemm_mma<2><<<dim3(DD / 128, BL / 128), 256>>>(ffh, w2h, b2,
                                                   Tb, Pb, nullptr, FF, DD);
    ln_kernel<false><<<BL, 256>>>(Pb, ln2g, ln2b, out, nullptr);
}